// round 10
// baseline (speedup 1.0000x reference)
#include <cuda_runtime.h>
#include <cuda_bf16.h>
#include <cstdint>
#include <math.h>

#define BB 8
#define CC 256
#define HWN 4096
#define RR 16
#define MQKV 288   // 256 v rows + 16 q rows + 16 k rows
#define MPAD 384   // padded to 3 tiles of 128

// ---------------- scratch (device globals; no allocations) ----------------
__device__ float g_avg[BB*CC];
__device__ float g_mx [BB*CC];
__device__ float g_gate[BB*CC];
__device__ float g_xg[(size_t)BB*CC*HWN];             // fp32 gated input (residual)
__device__ __nv_bfloat16 g_xgt[(size_t)BB*HWN*CC];    // bf16 gated input, transposed [b][n][c]
__device__ __nv_bfloat16 g_wh[MPAD*CC];               // packed bf16 [v;q;k;pad] weights
__device__ float g_bcat[MPAD];
__device__ __nv_bfloat16 g_qt[(size_t)BB*HWN*RR];     // q transposed [b][n][r]
__device__ __nv_bfloat16 g_kt[(size_t)BB*HWN*RR];
__device__ __nv_bfloat16 g_vh[(size_t)BB*CC*HWN];     // V bf16 [b][c][n]

// ---------------- asm helpers ----------------
__device__ __forceinline__ unsigned int sptr(const void* p) {
    return (unsigned int)__cvta_generic_to_shared(p);
}
#define CP16(dst, src) asm volatile("cp.async.cg.shared.global [%0], [%1], 16;\n" :: "r"(dst), "l"(src))
#define CP16P(dst, src) asm volatile("cp.async.cg.shared.global [%0], [%1], 16;\n" :: "r"(sptr(dst)), "l"(src))
#define CP_COMMIT()    asm volatile("cp.async.commit_group;\n")
#define CP_WAIT(n)     asm volatile("cp.async.wait_group %0;\n" :: "n"(n))
#define LDSM4(r0,r1,r2,r3,addr) \
    asm volatile("ldmatrix.sync.aligned.m8n8.x4.shared.b16 {%0,%1,%2,%3}, [%4];\n" \
        : "=r"(r0),"=r"(r1),"=r"(r2),"=r"(r3) : "r"(addr))
#define MMA16816(d,a,b0,b1) \
    asm volatile("mma.sync.aligned.m16n8k16.row.col.f32.bf16.bf16.f32 " \
        "{%0,%1,%2,%3}, {%4,%5,%6,%7}, {%8,%9}, {%0,%1,%2,%3};\n" \
        : "+f"(d[0]),"+f"(d[1]),"+f"(d[2]),"+f"(d[3]) \
        : "r"(a[0]),"r"(a[1]),"r"(a[2]),"r"(a[3]), "r"(b0),"r"(b1))

// ---------------- 1) avg+max pool over HW per (b,c) ----------------
__global__ __launch_bounds__(256) void k_pool(const float* __restrict__ x) {
    int bc = blockIdx.x;
    const float4* p = (const float4*)(x + (size_t)bc * HWN);
    float s = 0.f, m = -1e30f;
    for (int i = threadIdx.x; i < HWN/4; i += 256) {
        float4 v = p[i];
        s += v.x + v.y + v.z + v.w;
        m = fmaxf(m, fmaxf(fmaxf(v.x, v.y), fmaxf(v.z, v.w)));
    }
    __shared__ float ss[8], sm[8];
    for (int o = 16; o; o >>= 1) {
        s += __shfl_xor_sync(0xffffffffu, s, o);
        m = fmaxf(m, __shfl_xor_sync(0xffffffffu, m, o));
    }
    if ((threadIdx.x & 31) == 0) { ss[threadIdx.x >> 5] = s; sm[threadIdx.x >> 5] = m; }
    __syncthreads();
    if (threadIdx.x == 0) {
        float S = 0.f, M = -1e30f;
        for (int w = 0; w < 8; w++) { S += ss[w]; M = fmaxf(M, sm[w]); }
        g_avg[bc] = S * (1.f / HWN);
        g_mx[bc]  = M;
    }
}

// ---------------- 2) SE gate ----------------
__global__ __launch_bounds__(256) void k_gate(const float* __restrict__ w1,
                                              const float* __restrict__ w2) {
    int b = blockIdx.x, t = threadIdx.x;
    __shared__ float sa[CC], sx[CC], h[RR];
    sa[t] = g_avg[b*CC + t];
    sx[t] = g_mx [b*CC + t];
    __syncthreads();
    if (t < RR) {
        float da = 0.f, dm = 0.f;
        const float* w = w1 + t*CC;
        for (int c = 0; c < CC; c++) { da += w[c]*sa[c]; dm += w[c]*sx[c]; }
        h[t] = fmaxf(da, 0.f) + fmaxf(dm, 0.f);
    }
    __syncthreads();
    float g = 0.f;
    const float* w = w2 + t*RR;
    #pragma unroll
    for (int r = 0; r < RR; r++) g += w[r]*h[r];
    g_gate[b*CC + t] = 1.f / (1.f + __expf(-g));
}

// ---------------- 3) pack [v;q;k] weights -> bf16 (padded), biases fp32 ----------------
__global__ __launch_bounds__(256) void k_wpack(const float* __restrict__ vw,
                                               const float* __restrict__ qw,
                                               const float* __restrict__ kw,
                                               const float* __restrict__ vb,
                                               const float* __restrict__ qb,
                                               const float* __restrict__ kb) {
    int o = blockIdx.x, t = threadIdx.x;
    float val = 0.f, bias = 0.f;
    if (o < CC)            { val = vw[o*CC + t];          bias = vb[o]; }
    else if (o < CC + RR)  { val = qw[(o-CC)*CC + t];     bias = qb[o-CC]; }
    else if (o < MQKV)     { val = kw[(o-CC-RR)*CC + t];  bias = kb[o-CC-RR]; }
    g_wh[o*CC + t] = __float2bfloat16(val);
    if (t == 0) g_bcat[o] = bias;
}

// ---------------- 4) xg (fp32) + transposed bf16 xgt ----------------
__global__ __launch_bounds__(256) void k_xgt(const float* __restrict__ x) {
    int b = blockIdx.z, c0 = blockIdx.y*32, n0 = blockIdx.x*32;
    __shared__ float t[32][33];
    int tid = threadIdx.x;
    int tx = tid & 31, ty = tid >> 5;
    const float* xb  = x    + ((size_t)(b*CC + c0))*HWN + n0;
    float*       xgb = g_xg + ((size_t)(b*CC + c0))*HWN + n0;
    #pragma unroll
    for (int r = ty; r < 32; r += 8) {
        float g = g_gate[b*CC + c0 + r];
        float v = xb[(size_t)r*HWN + tx] * g;
        xgb[(size_t)r*HWN + tx] = v;
        t[r][tx] = v;
    }
    __syncthreads();
    __nv_bfloat16* dst = g_xgt + ((size_t)(b*HWN + n0))*CC + c0;
    int r2 = tid >> 3, ch = (tid & 7) * 4;
    union { __nv_bfloat162 h[2]; uint2 u; } pk;
    pk.h[0] = __floats2bfloat162_rn(t[ch+0][r2], t[ch+1][r2]);
    pk.h[1] = __floats2bfloat162_rn(t[ch+2][r2], t[ch+3][r2]);
    *(uint2*)(dst + (size_t)r2*CC + ch) = pk.u;
}

// ---------------- 5) fused QKV projection, bf16 mma (unchanged, proven) ----------------
__global__ __launch_bounds__(256) void k_qkv() {
    int b  = blockIdx.z;
    int o0 = blockIdx.y * 128;
    int n0 = blockIdx.x * 128;
    __shared__ __align__(16) __nv_bfloat16 As[2][128][40];
    __shared__ __align__(16) __nv_bfloat16 Bs[2][128][40];

    int tid = threadIdx.x, lane = tid & 31, wid = tid >> 5;
    int wm = wid >> 2, wn = wid & 3;

    const __nv_bfloat16* Ab = g_wh + (size_t)o0 * CC;
    const __nv_bfloat16* Bb = g_xgt + ((size_t)(b*HWN) + n0) * CC;

    int lr = tid >> 2;
    int lc = (tid & 3) * 8;

    float acc[4][4][4];
    #pragma unroll
    for (int mi = 0; mi < 4; mi++)
        #pragma unroll
        for (int ni = 0; ni < 4; ni++)
            #pragma unroll
            for (int e = 0; e < 4; e++) acc[mi][ni][e] = 0.f;

    #pragma unroll
    for (int pc = 0; pc < 2; pc++) {
        int k0 = pc * 32;
        CP16P(&As[pc][lr     ][lc], Ab + (size_t)(lr     )*CC + k0 + lc);
        CP16P(&As[pc][lr + 64][lc], Ab + (size_t)(lr + 64)*CC + k0 + lc);
        CP16P(&Bs[pc][lr     ][lc], Bb + (size_t)(lr     )*CC + k0 + lc);
        CP16P(&Bs[pc][lr + 64][lc], Bb + (size_t)(lr + 64)*CC + k0 + lc);
        CP_COMMIT();
    }

    #pragma unroll 1
    for (int it = 0; it < 8; it++) {
        int buf = it & 1;
        if (it == 7) { CP_WAIT(0); } else { CP_WAIT(1); }
        __syncthreads();
        #pragma unroll
        for (int ks = 0; ks < 2; ks++) {
            int k = ks * 16;
            int frow = lane & 15;
            int fcol = k + ((lane >> 4) << 3);
            uint32_t a[4][4];
            #pragma unroll
            for (int mi = 0; mi < 4; mi++) {
                unsigned int ad = sptr(&As[buf][wm*64 + mi*16 + frow][fcol]);
                LDSM4(a[mi][0], a[mi][1], a[mi][2], a[mi][3], ad);
            }
            uint32_t bf[2][4];
            #pragma unroll
            for (int nj = 0; nj < 2; nj++) {
                unsigned int ad = sptr(&Bs[buf][wn*32 + nj*16 + frow][fcol]);
                LDSM4(bf[nj][0], bf[nj][1], bf[nj][2], bf[nj][3], ad);
            }
            #pragma unroll
            for (int mi = 0; mi < 4; mi++)
                #pragma unroll
                for (int ni = 0; ni < 4; ni++) {
                    int nj = ni >> 1, h = ni & 1;
                    MMA16816(acc[mi][ni], a[mi], bf[nj][h], bf[nj][h+2]);
                }
        }
        __syncthreads();
        if (it + 2 < 8) {
            int k0 = (it + 2) * 32;
            CP16P(&As[buf][lr     ][lc], Ab + (size_t)(lr     )*CC + k0 + lc);
            CP16P(&As[buf][lr + 64][lc], Ab + (size_t)(lr + 64)*CC + k0 + lc);
            CP16P(&Bs[buf][lr     ][lc], Bb + (size_t)(lr     )*CC + k0 + lc);
            CP16P(&Bs[buf][lr + 64][lc], Bb + (size_t)(lr + 64)*CC + k0 + lc);
            CP_COMMIT();
        }
    }

    int qr = lane >> 2, qc = (lane & 3) * 2;
    #pragma unroll
    for (int mi = 0; mi < 4; mi++) {
        #pragma unroll
        for (int h = 0; h < 2; h++) {
            int r = o0 + wm*64 + mi*16 + qr + h*8;
            if (r >= MQKV) continue;
            float bias = g_bcat[r];
            if (r < CC) {
                __nv_bfloat16* dst = g_vh + ((size_t)(b*CC + r)) * HWN;
                #pragma unroll
                for (int ni = 0; ni < 4; ni++) {
                    int icol = n0 + wn*32 + ni*8 + qc;
                    *(__nv_bfloat162*)(dst + icol) =
                        __floats2bfloat162_rn(acc[mi][ni][2*h+0] + bias,
                                              acc[mi][ni][2*h+1] + bias);
                }
            } else {
                __nv_bfloat16* dst = (r < CC + RR) ? g_qt : g_kt;
                int rr = (r < CC + RR) ? (r - CC) : (r - CC - RR);
                #pragma unroll
                for (int ni = 0; ni < 4; ni++) {
                    int icol = n0 + wn*32 + ni*8 + qc;
                    dst[((size_t)(b*HWN) + icol    )*RR + rr] = __float2bfloat16(acc[mi][ni][2*h+0] + bias);
                    dst[((size_t)(b*HWN) + icol + 1)*RR + rr] = __float2bfloat16(acc[mi][ni][2*h+1] + bias);
                }
            }
        }
    }
}

// ---------------- 6) FUSED attention (mma.sync): scores+exp+rowsum+AV+epilogue ----------
// One CTA per (64-row i-tile, batch). D[256 c x 64 i] lives in registers
// (8 warps, 64c x 32i each = 64 fp32/thread). E exists only in a 9 KB smem
// tile per 64-j chunk. K/V double-buffered via cp.async.
//
// dynamic smem layout (bytes):
//   Qs   @ 0      : 64 rows x 48B                      = 3072
//   Ks   @ 3072   : 2 bufs x 64 rows x 48B             = 6144
//   Es   @ 9216   : 64 rows x 144B (72 bf16, padded)   = 9216
//   Vs   @ 18432  : 2 bufs x 256 rows x 144B           = 73728
//   rs2  @ 92160  : 2 x 64 fp32                        = 512
//   inv  @ 92672  : 64 fp32                            = 256
#define QS_OFF 0
#define KS_OFF 3072
#define ES_OFF 9216
#define VS_OFF 18432
#define RS2_OFF 92160
#define INV_OFF 92672
#define ATTN_SMEM 93184

__global__ __launch_bounds__(256, 1) void k_attn(const float* __restrict__ gamma,
                                                 float* __restrict__ out) {
    extern __shared__ __align__(16) char smx[];
    uint32_t smb = sptr(smx);
    int tid = threadIdx.x, lane = tid & 31, wid = tid >> 5;
    int b = blockIdx.y;
    int i0 = blockIdx.x * 64;

    int qr = lane >> 2, qc = (lane & 3) * 2;
    int frow = lane & 15, fcolh = (lane >> 4) << 3;

    // score-phase warp grid: wm (4) x wnj (2);  AV-phase: wc (4) x wi (2)
    int wm = wid >> 1, wnj = wid & 1;
    int wc = wid & 3,  wi  = wid >> 2;

    // load q i-tile: 64 rows x 16 r (32B rows -> 48B stride)
    if (tid < 128) {
        int row = tid >> 1, half = tid & 1;
        *(uint4*)(smx + QS_OFF + row*48 + half*16) =
            *(const uint4*)(g_qt + ((size_t)(b*HWN) + i0 + row)*RR + half*8);
    }

    // prologue: K + V for chunks 0, 1
    #pragma unroll
    for (int pc = 0; pc < 2; pc++) {
        if (tid < 128) {
            int row = tid >> 1, half = tid & 1;
            CP16(smb + KS_OFF + pc*3072 + row*48 + half*16,
                 g_kt + ((size_t)(b*HWN) + pc*64 + row)*RR + half*8);
        }
        #pragma unroll
        for (int v = 0; v < 8; v++) {
            int row = v*32 + (tid >> 3);
            int c16 = tid & 7;
            CP16(smb + VS_OFF + pc*36864 + row*144 + c16*16,
                 g_vh + ((size_t)(b*CC + row))*HWN + pc*64 + c16*8);
        }
        CP_COMMIT();
    }

    float acc[4][4][4];
    #pragma unroll
    for (int mi = 0; mi < 4; mi++)
        #pragma unroll
        for (int ni = 0; ni < 4; ni++)
            #pragma unroll
            for (int e = 0; e < 4; e++) acc[mi][ni][e] = 0.f;
    float rs0 = 0.f, rs1 = 0.f;

    #pragma unroll 1
    for (int jc = 0; jc < 64; jc++) {
        int buf = jc & 1;
        if (jc == 63) { CP_WAIT(0); } else { CP_WAIT(1); }
        __syncthreads();

        // ---- scores: warp (wm, wnj) computes S[16 i x 32 j] ----
        uint32_t aq[4];
        LDSM4(aq[0], aq[1], aq[2], aq[3],
              smb + QS_OFF + (wm*16 + frow)*48 + fcolh*2);
        uint32_t bk[2][4];
        #pragma unroll
        for (int nj = 0; nj < 2; nj++) {
            LDSM4(bk[nj][0], bk[nj][1], bk[nj][2], bk[nj][3],
                  smb + KS_OFF + buf*3072 + (wnj*32 + nj*16 + frow)*48 + fcolh*2);
        }
        float sacc[4][4];
        #pragma unroll
        for (int t = 0; t < 4; t++)
            #pragma unroll
            for (int e = 0; e < 4; e++) sacc[t][e] = 0.f;
        #pragma unroll
        for (int t = 0; t < 4; t++)
            MMA16816(sacc[t], aq, bk[t>>1][t&1], bk[t>>1][(t&1)+2]);

        // ---- exp -> Es smem (bf16), accumulate row sums of bf16-rounded vals ----
        #pragma unroll
        for (int t = 0; t < 4; t++) {
            int col = wnj*32 + t*8 + qc;
            int row = wm*16 + qr;
            __nv_bfloat162 p01 = __floats2bfloat162_rn(__expf(sacc[t][0]), __expf(sacc[t][1]));
            __nv_bfloat162 p23 = __floats2bfloat162_rn(__expf(sacc[t][2]), __expf(sacc[t][3]));
            asm volatile("st.shared.b32 [%0], %1;"
                :: "r"(smb + ES_OFF + row*144 + col*2), "r"(*(uint32_t*)&p01) : "memory");
            asm volatile("st.shared.b32 [%0], %1;"
                :: "r"(smb + ES_OFF + (row+8)*144 + col*2), "r"(*(uint32_t*)&p23) : "memory");
            float2 f01 = __bfloat1622float2(p01);
            float2 f23 = __bfloat1622float2(p23);
            rs0 += f01.x + f01.y;
            rs1 += f23.x + f23.y;
        }
        __syncthreads();

        // ---- AV: warp (wc, wi) does D[64c x 32i] += V[64c x 64j] * E[32i x 64j]^T ----
        #pragma unroll
        for (int ks = 0; ks < 4; ks++) {
            int fcol = ks*16 + fcolh;
            uint32_t av[4][4];
            #pragma unroll
            for (int mi = 0; mi < 4; mi++) {
                LDSM4(av[mi][0], av[mi][1], av[mi][2], av[mi][3],
                      smb + VS_OFF + buf*36864 + (wc*64 + mi*16 + frow)*144 + fcol*2);
            }
            uint32_t be[2][4];
            #pragma unroll
            for (int nj = 0; nj < 2; nj++) {
                LDSM4(be[nj][0], be[nj][1], be[nj][2], be[nj][3],
                      smb + ES_OFF + (wi*32 + nj*16 + frow)*144 + fcol*2);
            }
            #pragma unroll
            for (int mi = 0; mi < 4; mi++)
                #pragma unroll
                for (int ni = 0; ni < 4; ni++)
                    MMA16816(acc[mi][ni], av[mi], be[ni>>1][ni&1], be[ni>>1][(ni&1)+2]);
        }
        __syncthreads();

        // ---- prefetch chunk jc+2 into freed buf ----
        int pf = jc + 2;
        if (pf < 64) {
            if (tid < 128) {
                int row = tid >> 1, half = tid & 1;
                CP16(smb + KS_OFF + buf*3072 + row*48 + half*16,
                     g_kt + ((size_t)(b*HWN) + pf*64 + row)*RR + half*8);
            }
            #pragma unroll
            for (int v = 0; v < 8; v++) {
                int row = v*32 + (tid >> 3);
                int c16 = tid & 7;
                CP16(smb + VS_OFF + buf*36864 + row*144 + c16*16,
                     g_vh + ((size_t)(b*CC + row))*HWN + pf*64 + c16*8);
            }
            CP_COMMIT();
        }
    }

    // ---- row sums: combine j-halves, invert ----
    rs0 += __shfl_xor_sync(0xffffffffu, rs0, 1);
    rs0 += __shfl_xor_sync(0xffffffffu, rs0, 2);
    rs1 += __shfl_xor_sync(0xffffffffu, rs1, 1);
    rs1 += __shfl_xor_sync(0xffffffffu, rs1, 2);
    float* rs2 = (float*)(smx + RS2_OFF);
    float* inv = (float*)(smx + INV_OFF);
    if ((lane & 3) == 0) {
        rs2[wnj*64 + wm*16 + qr    ] = rs0;
        rs2[wnj*64 + wm*16 + qr + 8] = rs1;
    }
    __syncthreads();
    if (tid < 64) inv[tid] = 1.f / (rs2[tid] + rs2[64 + tid]);
    __syncthreads();

    // ---- epilogue: out = gamma * D * inv[i] + xg ----
    float gm = gamma[0];
    #pragma unroll
    for (int ni = 0; ni < 4; ni++) {
        int iloc = wi*32 + ni*8 + qc;
        float inv0 = inv[iloc], inv1 = inv[iloc + 1];
        #pragma unroll
        for (int mi = 0; mi < 4; mi++) {
            #pragma unroll
            for (int h = 0; h < 2; h++) {
                int c = wc*64 + mi*16 + qr + h*8;
                size_t base = ((size_t)(b*CC + c))*HWN + i0 + iloc;
                float2 xgv = *(const float2*)(g_xg + base);
                float2 o;
                o.x = gm * acc[mi][ni][2*h+0] * inv0 + xgv.x;
                o.y = gm * acc[mi][ni][2*h+1] * inv1 + xgv.y;
                *(float2*)(out + base) = o;
            }
        }
    }
}

// ---------------- launch ----------------
extern "C" void kernel_launch(void* const* d_in, const int* in_sizes, int n_in,
                              void* d_out, int out_size) {
    const float* x     = (const float*)d_in[0];
    const float* ca_w1 = (const float*)d_in[1];
    const float* ca_w2 = (const float*)d_in[2];
    const float* q_w   = (const float*)d_in[3];
    const float* q_b   = (const float*)d_in[4];
    const float* k_w   = (const float*)d_in[5];
    const float* k_b   = (const float*)d_in[6];
    const float* v_w   = (const float*)d_in[7];
    const float* v_b   = (const float*)d_in[8];
    const float* gamma = (const float*)d_in[9];
    float* out = (float*)d_out;

    cudaFuncSetAttribute(k_attn, cudaFuncAttributeMaxDynamicSharedMemorySize, ATTN_SMEM);

    k_pool  <<<BB*CC, 256>>>(x);
    k_wpack <<<MPAD, 256>>>(v_w, q_w, k_w, v_b, q_b, k_b);
    k_gate  <<<BB, 256>>>(ca_w1, ca_w2);
    k_xgt   <<<dim3(HWN/32, CC/32, BB), 256>>>(x);
    k_qkv   <<<dim3(HWN/128, MPAD/128, BB), 256>>>();
    k_attn  <<<dim3(HWN/64, BB), 256, ATTN_SMEM>>>(gamma, out);
}